// round 14
// baseline (speedup 1.0000x reference)
#include <cuda_runtime.h>
#include <cuda_fp16.h>
#include <math.h>
#include <stdint.h>

#define NN   30000
#define FIN  500
#define HIDN 16
#define NE   960000

// ---------------- scratch (device globals: no allocation allowed) ----------------
__device__ float g_h0[NN * HIDN];
__device__ float g_m1[NN * HIDN];
__device__ float g_acc1[NN * HIDN];
__device__ float g_m2[NN * 4];
__device__ float g_acc2[NN * 4];
__device__ float g_dinv[NN];
__device__ int   g_deg[NN];

__device__ __forceinline__ void red4(float* p, float4 v) {
    asm volatile("red.global.add.v4.f32 [%0], {%1,%2,%3,%4};"
                 :: "l"(p), "f"(v.x), "f"(v.y), "f"(v.z), "f"(v.w) : "memory");
}

__device__ __forceinline__ uint32_t smem_u32(const void* p) {
    uint32_t a;
    asm("{ .reg .u64 t; cvta.to.shared.u64 t, %1; cvt.u32.u64 %0, t; }" : "=r"(a) : "l"(p));
    return a;
}

__device__ __forceinline__ void mma_f16(float d[4],
                                        uint32_t a0, uint32_t a1, uint32_t a2, uint32_t a3,
                                        uint32_t b0, uint32_t b1) {
    asm volatile(
        "mma.sync.aligned.m16n8k16.row.col.f32.f16.f16.f32 "
        "{%0,%1,%2,%3}, {%4,%5,%6,%7}, {%8,%9}, {%0,%1,%2,%3};"
        : "+f"(d[0]), "+f"(d[1]), "+f"(d[2]), "+f"(d[3])
        : "r"(a0), "r"(a1), "r"(a2), "r"(a3), "r"(b0), "r"(b1));
}

__device__ __forceinline__ void ldm4(uint32_t& r0, uint32_t& r1, uint32_t& r2, uint32_t& r3,
                                     uint32_t addr) {
    asm volatile("ldmatrix.sync.aligned.m8n8.x4.shared.b16 {%0,%1,%2,%3}, [%4];"
                 : "=r"(r0), "=r"(r1), "=r"(r2), "=r"(r3) : "r"(addr));
}

// ---------------- conv1+relu+conv2+relu+maxpool via HMMA (fp16 single product) ----
// One block = 4 nodes sequentially, 128 threads (4 warps).
// conv1 computed in packed HFMA2 (both channels of a pair at once, bias-seeded,
// fp16 accumulate); y1 stored row-major [pos+1][16] fp16 in smem. A row p of the
// conv2 im2col GEMM is the contiguous window y1[p*16 .. +48).
// D[512,16] = A[512,48] x B[48,16] via m16n8k16, single fp16 product, fp32 acc.
// Per warp: 8 M-tiles in pairs (6 batched ldmatrix.x4, 4 indep MMA chains);
// running max in registers; rows p>=500 masked.
__global__ void __launch_bounds__(128) conv_mma_kernel(
    const float* __restrict__ x,
    const float* __restrict__ w1, const float* __restrict__ b1,
    const float* __restrict__ w2, const float* __restrict__ b2)
{
    __shared__ __align__(16) uint16_t y1h[514 * 16];
    __shared__ __align__(8)  __half2 xs2[516];   // duplicated pairs (v,v)
    __shared__ float redbuf[64];

    const int t    = threadIdx.x;
    const int wid  = t >> 5;
    const int lane = t & 31;

    // ---- one-time: zero pad rows (P=0 and P=501..513) and xs2 pads ----
    if (t < 16) y1h[t] = 0;
    for (int i = 501 * 16 + t; i < 514 * 16; i += 128) y1h[i] = 0;
    if (t < 2)  xs2[t] = __half2half2(__float2half(0.f));
    for (int i = 502 + t; i < 516; i += 128) xs2[i] = __half2half2(__float2half(0.f));

    // ---- B fragments (fp16; per thread, same across warps) ----
    // K-tile kt == tap; b0: i=(lane&3)*2, b1 holds k+8; n = nt*8 + lane/4
    uint32_t bh[3][2][2];
    {
        const int bn = lane >> 2;
        const int bi = (lane & 3) * 2;
        #pragma unroll
        for (int kt = 0; kt < 3; kt++)
            #pragma unroll
            for (int nt = 0; nt < 2; nt++) {
                const int n = nt * 8 + bn;
                #pragma unroll
                for (int rr = 0; rr < 2; rr++) {
                    const int i = bi + rr * 8;
                    float wa = __ldg(w2 + n * 48 + i * 3 + kt);
                    float wb = __ldg(w2 + n * 48 + (i + 1) * 3 + kt);
                    __half2 hh = __float22half2_rn(make_float2(wa, wb));
                    bh[kt][nt][rr] = *reinterpret_cast<uint32_t*>(&hh);
                }
            }
    }

    // ---- conv1 weights (packed half2 (w_ch, w_ch+1) per tap) ----
    const int i2 = t & 7;
    const int ch = 2 * i2;
    const __half2 wt0 = __float22half2_rn(make_float2(__ldg(w1 + ch * 3 + 0), __ldg(w1 + ch * 3 + 3)));
    const __half2 wt1 = __float22half2_rn(make_float2(__ldg(w1 + ch * 3 + 1), __ldg(w1 + ch * 3 + 4)));
    const __half2 wt2 = __float22half2_rn(make_float2(__ldg(w1 + ch * 3 + 2), __ldg(w1 + ch * 3 + 5)));
    const __half2 bb  = __float22half2_rn(make_float2(__ldg(b1 + ch), __ldg(b1 + ch + 1)));
    const __half2 zz  = __half2half2(__float2half(0.f));

    // ldmatrix lane addressing: row = lane&15, k-half = lane>>4 (8 halves = 16B)
    const uint32_t y1h_base = smem_u32(y1h);
    const uint32_t lmoff = (uint32_t)(((lane & 15) * 16 + (lane >> 4) * 8) * 2);

    const int nbase = blockIdx.x * 4;
    for (int rep = 0; rep < 4; rep++) {
        const int node = nbase + rep;

        if (t < 125) {
            float4 v = reinterpret_cast<const float4*>(x + (size_t)node * FIN)[t];
            xs2[2 + 4 * t] = __half2half2(__float2half_rn(v.x));
            xs2[3 + 4 * t] = __half2half2(__float2half_rn(v.y));
            xs2[4 + 4 * t] = __half2half2(__float2half_rn(v.z));
            xs2[5 + 4 * t] = __half2half2(__float2half_rn(v.w));
        }
        __syncthreads();   // xs2 ready; prev iter's redbuf fully consumed

        // ---- conv1 + relu -> y1 (fp16, packed HFMA2), rows P = p+1 ----
        #pragma unroll 2
        for (int p = (t >> 3); p < FIN; p += 16) {
            __half2 acc = bb;
            acc = __hfma2(wt2, xs2[p + 3], acc);
            acc = __hfma2(wt1, xs2[p + 2], acc);
            acc = __hfma2(wt0, xs2[p + 1], acc);
            acc = __hmax2(acc, zz);
            *reinterpret_cast<uint32_t*>(y1h + (p + 1) * 16 + ch) =
                *reinterpret_cast<const uint32_t*>(&acc);
        }
        __syncthreads();   // y1 ready

        // ---- GEMM + running max, tiles in pairs for MLP ----
        float mx[2][2] = {{-3.4e38f, -3.4e38f}, {-3.4e38f, -3.4e38f}};  // [nt][even/odd col]
        #pragma unroll
        for (int jj = 0; jj < 8; jj += 2) {
            const int tile0 = wid * 8 + jj;
            // batch all 6 ldmatrix first (independent -> MLP)
            uint32_t fa[2][3][4];
            #pragma unroll
            for (int u = 0; u < 2; u++) {
                const uint32_t abyte = (uint32_t)((tile0 + u) * 16 * 32) + lmoff;
                #pragma unroll
                for (int kt = 0; kt < 3; kt++)
                    ldm4(fa[u][kt][0], fa[u][kt][1], fa[u][kt][2], fa[u][kt][3],
                         y1h_base + abyte + (uint32_t)(kt * 32));
            }
            // 4 independent MMA chains (2 tiles x 2 N-halves), 3 deep each
            float d[2][2][4];
            #pragma unroll
            for (int u = 0; u < 2; u++)
                #pragma unroll
                for (int nt = 0; nt < 2; nt++)
                    #pragma unroll
                    for (int q = 0; q < 4; q++) d[u][nt][q] = 0.f;
            #pragma unroll
            for (int kt = 0; kt < 3; kt++)
                #pragma unroll
                for (int u = 0; u < 2; u++) {
                    mma_f16(d[u][0], fa[u][kt][0], fa[u][kt][1], fa[u][kt][2], fa[u][kt][3],
                            bh[kt][0][0], bh[kt][0][1]);
                    mma_f16(d[u][1], fa[u][kt][0], fa[u][kt][1], fa[u][kt][2], fa[u][kt][3],
                            bh[kt][1][0], bh[kt][1][1]);
                }
            #pragma unroll
            for (int u = 0; u < 2; u++) {
                const int tile = tile0 + u;
                if (tile != 31) {
                    #pragma unroll
                    for (int nt = 0; nt < 2; nt++) {
                        mx[nt][0] = fmaxf(mx[nt][0], fmaxf(d[u][nt][0], d[u][nt][2]));
                        mx[nt][1] = fmaxf(mx[nt][1], fmaxf(d[u][nt][1], d[u][nt][3]));
                    }
                } else if (lane < 16) {
                    // rows 496..499 live in d[...][0..1] of lanes 0..15; 500..511 masked
                    #pragma unroll
                    for (int nt = 0; nt < 2; nt++) {
                        mx[nt][0] = fmaxf(mx[nt][0], d[u][nt][0]);
                        mx[nt][1] = fmaxf(mx[nt][1], d[u][nt][1]);
                    }
                }
            }
        }

        // butterfly max across lanes sharing (lane&3): xor 4, 8, 16
        #pragma unroll
        for (int off = 4; off <= 16; off <<= 1) {
            #pragma unroll
            for (int nt = 0; nt < 2; nt++) {
                mx[nt][0] = fmaxf(mx[nt][0], __shfl_xor_sync(0xffffffffu, mx[nt][0], off));
                mx[nt][1] = fmaxf(mx[nt][1], __shfl_xor_sync(0xffffffffu, mx[nt][1], off));
            }
        }
        if (lane < 4) {
            redbuf[wid * 16 + 2 * lane]         = mx[0][0];
            redbuf[wid * 16 + 2 * lane + 1]     = mx[0][1];
            redbuf[wid * 16 + 8 + 2 * lane]     = mx[1][0];
            redbuf[wid * 16 + 8 + 2 * lane + 1] = mx[1][1];
        }
        __syncthreads();   // redbuf ready
        if (t < 16) {
            float m = fmaxf(fmaxf(redbuf[t], redbuf[16 + t]),
                            fmaxf(redbuf[32 + t], redbuf[48 + t]));
            g_h0[node * HIDN + t] = fmaxf(m + __ldg(b2 + t), 0.f);
        }
        // next iteration's first __syncthreads orders redbuf reads vs rewrites
    }
}

// ---------------- GCN kernels (unchanged) ----------------
__global__ void zero_kernel() {
    int i = blockIdx.x * blockDim.x + threadIdx.x;
    if (i < NN * HIDN) g_acc1[i] = 0.f;
    if (i < NN * 4)    g_acc2[i] = 0.f;
    if (i < NN)        g_deg[i]  = 0;
}

__global__ void deg_kernel(const int* __restrict__ ei) {
    int e = blockIdx.x * blockDim.x + threadIdx.x;
    if (e < NE) atomicAdd(&g_deg[ei[NE + e]], 1);
}

__global__ void m1_kernel(const float* __restrict__ w) {
    int gid = blockIdx.x * blockDim.x + threadIdx.x;
    if (gid >= NN * HIDN) return;
    int v = gid >> 4, j = gid & 15;
    float dinv = rsqrtf((float)g_deg[v] + 1.0f);
    if (j == 0) g_dinv[v] = dinv;
    float s = 0.f;
    #pragma unroll
    for (int i = 0; i < HIDN; i++)
        s = fmaf(g_h0[v * HIDN + i], __ldg(w + i * HIDN + j), s);
    g_m1[gid] = s * dinv;
}

__global__ void scatter1_kernel(const int* __restrict__ ei) {
    int e = blockIdx.x * blockDim.x + threadIdx.x;
    if (e >= NE) return;
    int s = ei[e], d = ei[NE + e];
    const float4* m = reinterpret_cast<const float4*>(g_m1 + s * HIDN);
    float4 v0 = m[0], v1 = m[1], v2 = m[2], v3 = m[3];
    float* a = g_acc1 + d * HIDN;
    red4(a, v0); red4(a + 4, v1); red4(a + 8, v2); red4(a + 12, v3);
}

__global__ void out1m2_kernel(const float* __restrict__ gb1, const float* __restrict__ gw2) {
    int v = blockIdx.x * blockDim.x + threadIdx.x;
    if (v >= NN) return;
    float dinv = g_dinv[v];
    const float4* a = reinterpret_cast<const float4*>(g_acc1 + v * HIDN);
    const float4* m = reinterpret_cast<const float4*>(g_m1 + v * HIDN);
    float o1[HIDN];
    #pragma unroll
    for (int q = 0; q < 4; q++) {
        float4 av = a[q], mv = m[q];
        o1[4 * q + 0] = fmaxf(dinv * (av.x + mv.x) + __ldg(gb1 + 4 * q + 0), 0.f);
        o1[4 * q + 1] = fmaxf(dinv * (av.y + mv.y) + __ldg(gb1 + 4 * q + 1), 0.f);
        o1[4 * q + 2] = fmaxf(dinv * (av.z + mv.z) + __ldg(gb1 + 4 * q + 2), 0.f);
        o1[4 * q + 3] = fmaxf(dinv * (av.w + mv.w) + __ldg(gb1 + 4 * q + 3), 0.f);
    }
    float s0 = 0.f, s1 = 0.f, s2 = 0.f;
    #pragma unroll
    for (int j = 0; j < HIDN; j++) {
        float h = o1[j];
        s0 = fmaf(h, __ldg(gw2 + j * 3 + 0), s0);
        s1 = fmaf(h, __ldg(gw2 + j * 3 + 1), s1);
        s2 = fmaf(h, __ldg(gw2 + j * 3 + 2), s2);
    }
    reinterpret_cast<float4*>(g_m2)[v] = make_float4(s0 * dinv, s1 * dinv, s2 * dinv, 0.f);
}

__global__ void scatter2_kernel(const int* __restrict__ ei) {
    int e = blockIdx.x * blockDim.x + threadIdx.x;
    if (e >= NE) return;
    int s = ei[e], d = ei[NE + e];
    float4 v = reinterpret_cast<const float4*>(g_m2)[s];
    red4(g_acc2 + d * 4, v);
}

__global__ void final_kernel(const float* __restrict__ gb2, float* __restrict__ out) {
    int v = blockIdx.x * blockDim.x + threadIdx.x;
    if (v >= NN) return;
    float dinv = g_dinv[v];
    float4 a = reinterpret_cast<const float4*>(g_acc2)[v];
    float4 m = reinterpret_cast<const float4*>(g_m2)[v];
    float z0 = dinv * (a.x + m.x) + __ldg(gb2 + 0);
    float z1 = dinv * (a.y + m.y) + __ldg(gb2 + 1);
    float z2 = dinv * (a.z + m.z) + __ldg(gb2 + 2);
    float mx = fmaxf(z0, fmaxf(z1, z2));
    float l = logf(expf(z0 - mx) + expf(z1 - mx) + expf(z2 - mx));
    out[v * 3 + 0] = z0 - mx - l;
    out[v * 3 + 1] = z1 - mx - l;
    out[v * 3 + 2] = z2 - mx - l;
}

// ---------------- launch ----------------
extern "C" void kernel_launch(void* const* d_in, const int* in_sizes, int n_in,
                              void* d_out, int out_size) {
    const float* x   = (const float*)d_in[0];
    const float* c1w = (const float*)d_in[1];
    const float* c1b = (const float*)d_in[2];
    const float* c2w = (const float*)d_in[3];
    const float* c2b = (const float*)d_in[4];
    const float* g1w = (const float*)d_in[5];
    const float* g1b = (const float*)d_in[6];
    const float* g2w = (const float*)d_in[7];
    const float* g2b = (const float*)d_in[8];
    const int*   ei  = (const int*)d_in[9];
    float* out = (float*)d_out;

    zero_kernel<<<(NN * HIDN + 255) / 256, 256>>>();
    conv_mma_kernel<<<NN / 4, 128>>>(x, c1w, c1b, c2w, c2b);
    deg_kernel<<<(NE + 255) / 256, 256>>>(ei);
    m1_kernel<<<(NN * HIDN + 255) / 256, 256>>>(g1w);
    scatter1_kernel<<<(NE + 255) / 256, 256>>>(ei);
    out1m2_kernel<<<(NN + 127) / 128, 128>>>(g1b, g2w);
    scatter2_kernel<<<(NE + 255) / 256, 256>>>(ei);
    final_kernel<<<(NN + 127) / 128, 128>>>(g2b, out);
}

// round 15
// speedup vs baseline: 1.0571x; 1.0571x over previous
#include <cuda_runtime.h>
#include <cuda_fp16.h>
#include <math.h>
#include <stdint.h>

#define NN   30000
#define FIN  500
#define HIDN 16
#define NE   960000

// ---------------- scratch (device globals: no allocation allowed) ----------------
__device__ float g_h0[NN * HIDN];
__device__ float g_m1[NN * HIDN];
__device__ float g_acc1[NN * HIDN];
__device__ float g_m2[NN * 4];
__device__ float g_acc2[NN * 4];
__device__ float g_dinv[NN];
__device__ int   g_deg[NN];

__device__ __forceinline__ void red4(float* p, float4 v) {
    asm volatile("red.global.add.v4.f32 [%0], {%1,%2,%3,%4};"
                 :: "l"(p), "f"(v.x), "f"(v.y), "f"(v.z), "f"(v.w) : "memory");
}

__device__ __forceinline__ uint32_t smem_u32(const void* p) {
    uint32_t a;
    asm("{ .reg .u64 t; cvta.to.shared.u64 t, %1; cvt.u32.u64 %0, t; }" : "=r"(a) : "l"(p));
    return a;
}

__device__ __forceinline__ void mma_f16(float d[4],
                                        uint32_t a0, uint32_t a1, uint32_t a2, uint32_t a3,
                                        uint32_t b0, uint32_t b1) {
    asm volatile(
        "mma.sync.aligned.m16n8k16.row.col.f32.f16.f16.f32 "
        "{%0,%1,%2,%3}, {%4,%5,%6,%7}, {%8,%9}, {%0,%1,%2,%3};"
        : "+f"(d[0]), "+f"(d[1]), "+f"(d[2]), "+f"(d[3])
        : "r"(a0), "r"(a1), "r"(a2), "r"(a3), "r"(b0), "r"(b1));
}

__device__ __forceinline__ void ldm4(uint32_t& r0, uint32_t& r1, uint32_t& r2, uint32_t& r3,
                                     uint32_t addr) {
    asm volatile("ldmatrix.sync.aligned.m8n8.x4.shared.b16 {%0,%1,%2,%3}, [%4];"
                 : "=r"(r0), "=r"(r1), "=r"(r2), "=r"(r3) : "r"(addr));
}

// ---------------- conv1+relu+conv2+relu+maxpool via HMMA (fp16 single product) ----
// (R13 structure, proven 217.9us / rel_err 3.5e-5.)
// One block = 4 nodes sequentially, 128 threads (4 warps).
// y1 (conv1 output, relu'd, fp16) stored row-major [pos+1][16] in smem; A row p of
// the conv2 im2col GEMM is the contiguous window y1[p*16 .. +48).
// D[512,16] = A[512,48] x B[48,16] via m16n8k16, single fp16 product, fp32 acc.
// Per warp: 8 M-tiles in pairs (6 batched ldmatrix.x4, 4 indep MMA chains);
// running max in registers; rows p>=500 masked.
// Extra duty: each CTA zeroes its 4 g_deg entries (deg_kernel runs after conv).
__global__ void __launch_bounds__(128) conv_mma_kernel(
    const float* __restrict__ x,
    const float* __restrict__ w1, const float* __restrict__ b1,
    const float* __restrict__ w2, const float* __restrict__ b2)
{
    __shared__ __align__(16) uint16_t y1h[514 * 16];
    __shared__ __align__(16) float xs[516];
    __shared__ float redbuf[64];

    const int t    = threadIdx.x;
    const int wid  = t >> 5;
    const int lane = t & 31;

    // ---- fold zero_kernel's deg part in here ----
    if (t < 4) g_deg[blockIdx.x * 4 + t] = 0;

    // ---- one-time: zero pad rows (P=0 and P=501..513) and xs pads ----
    if (t < 16) y1h[t] = 0;
    for (int i = 501 * 16 + t; i < 514 * 16; i += 128) y1h[i] = 0;
    if (t < 2)  xs[t] = 0.f;
    for (int i = 502 + t; i < 516; i += 128) xs[i] = 0.f;

    // ---- B fragments (fp16; per thread, same across warps) ----
    uint32_t bh[3][2][2];
    {
        const int bn = lane >> 2;
        const int bi = (lane & 3) * 2;
        #pragma unroll
        for (int kt = 0; kt < 3; kt++)
            #pragma unroll
            for (int nt = 0; nt < 2; nt++) {
                const int n = nt * 8 + bn;
                #pragma unroll
                for (int rr = 0; rr < 2; rr++) {
                    const int i = bi + rr * 8;
                    float wa = __ldg(w2 + n * 48 + i * 3 + kt);
                    float wb = __ldg(w2 + n * 48 + (i + 1) * 3 + kt);
                    __half2 hh = __float22half2_rn(make_float2(wa, wb));
                    bh[kt][nt][rr] = *reinterpret_cast<uint32_t*>(&hh);
                }
            }
    }

    // ---- conv1 weights for this thread's channel pair (fp32, two indep chains) ----
    const int i2 = t & 7;
    const int ch = 2 * i2;
    const float u00 = __ldg(w1 + ch * 3 + 0), u01 = __ldg(w1 + ch * 3 + 1), u02 = __ldg(w1 + ch * 3 + 2);
    const float u10 = __ldg(w1 + ch * 3 + 3), u11 = __ldg(w1 + ch * 3 + 4), u12 = __ldg(w1 + ch * 3 + 5);
    const float ub0 = __ldg(b1 + ch), ub1 = __ldg(b1 + ch + 1);

    // ldmatrix lane addressing: row = lane&15, k-half = lane>>4 (8 halves = 16B)
    const uint32_t y1h_base = smem_u32(y1h);
    const uint32_t lmoff = (uint32_t)(((lane & 15) * 16 + (lane >> 4) * 8) * 2);

    const int nbase = blockIdx.x * 4;
    for (int rep = 0; rep < 4; rep++) {
        const int node = nbase + rep;

        if (t < 125) {
            float4 v = reinterpret_cast<const float4*>(x + (size_t)node * FIN)[t];
            xs[2 + 4 * t] = v.x; xs[3 + 4 * t] = v.y;
            xs[4 + 4 * t] = v.z; xs[5 + 4 * t] = v.w;
        }
        __syncthreads();   // xs ready; prev iter's redbuf fully consumed

        // ---- conv1 + relu -> y1 (fp16), rows P = p+1 ----
        for (int p = (t >> 3); p < FIN; p += 16) {
            const float xa = xs[p + 1], xb = xs[p + 2], xc = xs[p + 3];
            const float y0 = fmaxf(fmaf(u00, xa, fmaf(u01, xb, fmaf(u02, xc, ub0))), 0.f);
            const float y1 = fmaxf(fmaf(u10, xa, fmaf(u11, xb, fmaf(u12, xc, ub1))), 0.f);
            __half2 hh = __float22half2_rn(make_float2(y0, y1));
            *reinterpret_cast<uint32_t*>(y1h + (p + 1) * 16 + ch) =
                *reinterpret_cast<uint32_t*>(&hh);
        }
        __syncthreads();   // y1 ready

        // ---- GEMM + running max, tiles in pairs for MLP ----
        float mx[2][2] = {{-3.4e38f, -3.4e38f}, {-3.4e38f, -3.4e38f}};  // [nt][even/odd col]
        #pragma unroll
        for (int jj = 0; jj < 8; jj += 2) {
            const int tile0 = wid * 8 + jj;
            uint32_t fa[2][3][4];
            #pragma unroll
            for (int u = 0; u < 2; u++) {
                const uint32_t abyte = (uint32_t)((tile0 + u) * 16 * 32) + lmoff;
                #pragma unroll
                for (int kt = 0; kt < 3; kt++)
                    ldm4(fa[u][kt][0], fa[u][kt][1], fa[u][kt][2], fa[u][kt][3],
                         y1h_base + abyte + (uint32_t)(kt * 32));
            }
            float d[2][2][4];
            #pragma unroll
            for (int u = 0; u < 2; u++)
                #pragma unroll
                for (int nt = 0; nt < 2; nt++)
                    #pragma unroll
                    for (int q = 0; q < 4; q++) d[u][nt][q] = 0.f;
            #pragma unroll
            for (int kt = 0; kt < 3; kt++)
                #pragma unroll
                for (int u = 0; u < 2; u++) {
                    mma_f16(d[u][0], fa[u][kt][0], fa[u][kt][1], fa[u][kt][2], fa[u][kt][3],
                            bh[kt][0][0], bh[kt][0][1]);
                    mma_f16(d[u][1], fa[u][kt][0], fa[u][kt][1], fa[u][kt][2], fa[u][kt][3],
                            bh[kt][1][0], bh[kt][1][1]);
                }
            #pragma unroll
            for (int u = 0; u < 2; u++) {
                const int tile = tile0 + u;
                if (tile != 31) {
                    #pragma unroll
                    for (int nt = 0; nt < 2; nt++) {
                        mx[nt][0] = fmaxf(mx[nt][0], fmaxf(d[u][nt][0], d[u][nt][2]));
                        mx[nt][1] = fmaxf(mx[nt][1], fmaxf(d[u][nt][1], d[u][nt][3]));
                    }
                } else if (lane < 16) {
                    // rows 496..499 live in d[...][0..1] of lanes 0..15; 500..511 masked
                    #pragma unroll
                    for (int nt = 0; nt < 2; nt++) {
                        mx[nt][0] = fmaxf(mx[nt][0], d[u][nt][0]);
                        mx[nt][1] = fmaxf(mx[nt][1], d[u][nt][1]);
                    }
                }
            }
        }

        // butterfly max across lanes sharing (lane&3): xor 4, 8, 16
        #pragma unroll
        for (int off = 4; off <= 16; off <<= 1) {
            #pragma unroll
            for (int nt = 0; nt < 2; nt++) {
                mx[nt][0] = fmaxf(mx[nt][0], __shfl_xor_sync(0xffffffffu, mx[nt][0], off));
                mx[nt][1] = fmaxf(mx[nt][1], __shfl_xor_sync(0xffffffffu, mx[nt][1], off));
            }
        }
        if (lane < 4) {
            redbuf[wid * 16 + 2 * lane]         = mx[0][0];
            redbuf[wid * 16 + 2 * lane + 1]     = mx[0][1];
            redbuf[wid * 16 + 8 + 2 * lane]     = mx[1][0];
            redbuf[wid * 16 + 8 + 2 * lane + 1] = mx[1][1];
        }
        __syncthreads();   // redbuf ready
        if (t < 16) {
            float m = fmaxf(fmaxf(redbuf[t], redbuf[16 + t]),
                            fmaxf(redbuf[32 + t], redbuf[48 + t]));
            g_h0[node * HIDN + t] = fmaxf(m + __ldg(b2 + t), 0.f);
        }
        // next iteration's first __syncthreads orders redbuf reads vs rewrites
    }
}

// ---------------- GCN kernels ----------------
__global__ void deg_kernel(const int* __restrict__ ei) {
    int e2 = blockIdx.x * blockDim.x + threadIdx.x;
    if (e2 >= NE / 2) return;
    int2 d2 = reinterpret_cast<const int2*>(ei + NE)[e2];
    atomicAdd(&g_deg[d2.x], 1);
    atomicAdd(&g_deg[d2.y], 1);
}

// m1[v][j] = dinv[v] * sum_i h0[v][i]*W1[i][j]; also zeroes acc1 (pre-scatter1)
__global__ void m1_kernel(const float* __restrict__ w) {
    int gid = blockIdx.x * blockDim.x + threadIdx.x;
    if (gid >= NN * HIDN) return;
    g_acc1[gid] = 0.f;
    int v = gid >> 4, j = gid & 15;
    float dinv = rsqrtf((float)g_deg[v] + 1.0f);
    if (j == 0) g_dinv[v] = dinv;
    float s = 0.f;
    #pragma unroll
    for (int i = 0; i < HIDN; i++)
        s = fmaf(g_h0[v * HIDN + i], __ldg(w + i * HIDN + j), s);
    g_m1[gid] = s * dinv;
}

__global__ void scatter1_kernel(const int* __restrict__ ei) {
    int e2 = blockIdx.x * blockDim.x + threadIdx.x;
    if (e2 >= NE / 2) return;
    int2 s2 = reinterpret_cast<const int2*>(ei)[e2];
    int2 d2 = reinterpret_cast<const int2*>(ei + NE)[e2];
    const float4* ma = reinterpret_cast<const float4*>(g_m1 + s2.x * HIDN);
    const float4* mb = reinterpret_cast<const float4*>(g_m1 + s2.y * HIDN);
    float4 a0 = ma[0], a1 = ma[1], a2 = ma[2], a3 = ma[3];
    float4 b0 = mb[0], b1 = mb[1], b2 = mb[2], b3 = mb[3];
    float* pa = g_acc1 + d2.x * HIDN;
    float* pb = g_acc1 + d2.y * HIDN;
    red4(pa, a0); red4(pa + 4, a1); red4(pa + 8, a2); red4(pa + 12, a3);
    red4(pb, b0); red4(pb + 4, b1); red4(pb + 8, b2); red4(pb + 12, b3);
}

// out1 = relu(dinv*(acc1+m1)+b1g); m2 = (out1@W2g)*dinv; also zeroes acc2
__global__ void out1m2_kernel(const float* __restrict__ gb1, const float* __restrict__ gw2) {
    int v = blockIdx.x * blockDim.x + threadIdx.x;
    if (v >= NN) return;
    reinterpret_cast<float4*>(g_acc2)[v] = make_float4(0.f, 0.f, 0.f, 0.f);
    float dinv = g_dinv[v];
    const float4* a = reinterpret_cast<const float4*>(g_acc1 + v * HIDN);
    const float4* m = reinterpret_cast<const float4*>(g_m1 + v * HIDN);
    float o1[HIDN];
    #pragma unroll
    for (int q = 0; q < 4; q++) {
        float4 av = a[q], mv = m[q];
        o1[4 * q + 0] = fmaxf(dinv * (av.x + mv.x) + __ldg(gb1 + 4 * q + 0), 0.f);
        o1[4 * q + 1] = fmaxf(dinv * (av.y + mv.y) + __ldg(gb1 + 4 * q + 1), 0.f);
        o1[4 * q + 2] = fmaxf(dinv * (av.z + mv.z) + __ldg(gb1 + 4 * q + 2), 0.f);
        o1[4 * q + 3] = fmaxf(dinv * (av.w + mv.w) + __ldg(gb1 + 4 * q + 3), 0.f);
    }
    float s0 = 0.f, s1 = 0.f, s2 = 0.f;
    #pragma unroll
    for (int j = 0; j < HIDN; j++) {
        float h = o1[j];
        s0 = fmaf(h, __ldg(gw2 + j * 3 + 0), s0);
        s1 = fmaf(h, __ldg(gw2 + j * 3 + 1), s1);
        s2 = fmaf(h, __ldg(gw2 + j * 3 + 2), s2);
    }
    reinterpret_cast<float4*>(g_m2)[v] = make_float4(s0 * dinv, s1 * dinv, s2 * dinv, 0.f);
}

__global__ void scatter2_kernel(const int* __restrict__ ei) {
    int e2 = blockIdx.x * blockDim.x + threadIdx.x;
    if (e2 >= NE / 2) return;
    int2 s2 = reinterpret_cast<const int2*>(ei)[e2];
    int2 d2 = reinterpret_cast<const int2*>(ei + NE)[e2];
    float4 va = reinterpret_cast<const float4*>(g_m2)[s2.x];
    float4 vb = reinterpret_cast<const float4*>(g_m2)[s2.y];
    red4(g_acc2 + d2.x * 4, va);
    red4(g_acc2 + d2.y * 4, vb);
}

__global__ void final_kernel(const float* __restrict__ gb2, float* __restrict__ out) {
    int v = blockIdx.x * blockDim.x + threadIdx.x;
    if (v >= NN) return;
    float dinv = g_dinv[v];
    float4 a = reinterpret_cast<const float4*>(g_acc2)[v];
    float4 m = reinterpret_cast<const float4*>(g_m2)[v];
    float z0 = dinv * (a.x + m.x) + __ldg(gb2 + 0);
    float z1 = dinv * (a.y + m.y) + __ldg(gb2 + 1);
    float z2 = dinv * (a.z + m.z) + __ldg(gb2 + 2);
    float mx = fmaxf(z0, fmaxf(z1, z2));
    float l = __logf(__expf(z0 - mx) + __expf(z1 - mx) + __expf(z2 - mx));
    out[v * 3 + 0] = z0 - mx - l;
    out[v * 3 + 1] = z1 - mx - l;
    out[v * 3 + 2] = z2 - mx - l;
}

// ---------------- launch ----------------
extern "C" void kernel_launch(void* const* d_in, const int* in_sizes, int n_in,
                              void* d_out, int out_size) {
    const float* x   = (const float*)d_in[0];
    const float* c1w = (const float*)d_in[1];
    const float* c1b = (const float*)d_in[2];
    const float* c2w = (const float*)d_in[3];
    const float* c2b = (const float*)d_in[4];
    const float* g1w = (const float*)d_in[5];
    const float* g1b = (const float*)d_in[6];
    const float* g2w = (const float*)d_in[7];
    const float* g2b = (const float*)d_in[8];
    const int*   ei  = (const int*)d_in[9];
    float* out = (float*)d_out;

    conv_mma_kernel<<<NN / 4, 128>>>(x, c1w, c1b, c2w, c2b);
    deg_kernel<<<(NE / 2 + 255) / 256, 256>>>(ei);
    m1_kernel<<<(NN * HIDN + 255) / 256, 256>>>(g1w);
    scatter1_kernel<<<(NE / 2 + 255) / 256, 256>>>(ei);
    out1m2_kernel<<<(NN + 127) / 128, 128>>>(g1b, g2w);
    scatter2_kernel<<<(NE / 2 + 255) / 256, 256>>>(ei);
    final_kernel<<<(NN + 127) / 128, 128>>>(g2b, out);
}